// round 16
// baseline (speedup 1.0000x reference)
#include <cuda_runtime.h>

#define D      3072
#define BATCH  512
#define NC     100
#define RS     96      // row splits for column-sum kernel
#define RROWS  32      // rows per split (96*32 = 3072)
#define BK     64      // GEMM k-tile per CTA (single smem stage)
#define NSPLIT 48      // D / BK
#define BM     64      // GEMM m-tile
#define MT     8       // BATCH / BM
#define ZSTR   65      // Zs row stride (>= BK+1; 65 mod 32 = 1 -> conflict-free)
#define WTS    104     // Wt row stride (floats), 16B-aligned rows
#define OSTR   101     // epilogue staging stride

// ---- device scratch (static, no allocation) ----
__device__ float g_pA[RS * D];
__device__ float g_pB[RS * D];
__device__ float g_fcrow[NC];
__device__ float g_part1;
__device__ float g_scratch[NSPLIT * BATCH * NC];   // 9.8 MB

// ---- f32x2 packed-FMA helpers (sm_103a FFMA2, rt2 confirmed by profile) ----
__device__ __forceinline__ unsigned long long pk2(float lo, float hi) {
    unsigned long long r;
    asm("mov.b64 %0, {%1, %2};" : "=l"(r) : "f"(lo), "f"(hi));
    return r;
}
__device__ __forceinline__ void fma2(unsigned long long& d,
                                     unsigned long long a,
                                     unsigned long long b) {
    asm("fma.rn.f32x2 %0, %1, %2, %0;" : "+l"(d) : "l"(a), "l"(b));
}
__device__ __forceinline__ float2 up2(unsigned long long v) {
    float2 f;
    asm("mov.b64 {%0, %1}, %2;" : "=f"(f.x), "=f"(f.y) : "l"(v));
    return f;
}

// ---- FMA-pipe sincos (validated rel_err ~4.5e-7) ----
__device__ __forceinline__ void fast_sincos(float x, float& sn, float& cs) {
    const float BIGMAGIC = 12582912.0f;               // 1.5 * 2^23
    float y = fmaf(x, 0.63661977236758134f, BIGMAGIC);
    unsigned q = __float_as_uint(y);
    float n = y - BIGMAGIC;
    float r = fmaf(n, -1.57079637050628662109375f, x);
    r = fmaf(n, 4.37113900018624283e-8f, r);
    float r2 = r * r;
    float ps = fmaf(r2, -1.9515295891e-4f, 8.3321608736e-3f);
    ps = fmaf(r2, ps, -1.6666654611e-1f);
    float sinp = fmaf(r * r2, ps, r);
    float pc = fmaf(r2, 2.443315711809948e-5f, -1.388731625493765e-3f);
    pc = fmaf(r2, pc, 4.166664568298827e-2f);
    pc = fmaf(r2, pc, -0.5f);
    float cosp = fmaf(r2, pc, 1.0f);
    bool swap = (q & 1u);
    float us = swap ? cosp : sinp;
    float uc = swap ? sinp : cosp;
    sn = __uint_as_float(__float_as_uint(us) ^ ((q & 2u) << 30));
    cs = __uint_as_float(__float_as_uint(uc) ^ (((q + 1u) & 2u) << 30));
}

// ============================================================
// K1a: partial column sums of a/b. grid (3, 96, 2), block 256.
// __launch_bounds__(256,2) -> 128-reg cap so the vbuf[8] batch of
// LDG.128 really stays in registers (forced MLP=8).
// 221K threads x 32 rows each.
// ============================================================
__global__ __launch_bounds__(256, 2)
void k1_colsum(const float4* __restrict__ a, const float4* __restrict__ b) {
    int d4 = blockIdx.x * 256 + threadIdx.x;       // 0..767
    int rs = blockIdx.y;                           // 0..95
    const float4* src = (blockIdx.z == 0) ? a : b;
    float*        dst = (blockIdx.z == 0) ? g_pA : g_pB;
    const float4* p = src + rs * RROWS * (D / 4) + d4;
    float4 acc0 = make_float4(0.f, 0.f, 0.f, 0.f);
    float4 acc1 = make_float4(0.f, 0.f, 0.f, 0.f);
    float4 vbuf[8];
#pragma unroll
    for (int batch = 0; batch < RROWS / 8; batch++) {
#pragma unroll
        for (int j = 0; j < 8; j++)
            vbuf[j] = __ldcs(&p[(batch * 8 + j) * (D / 4)]);
#pragma unroll
        for (int j = 0; j < 8; j += 2) {
            acc0.x += vbuf[j].x;     acc0.y += vbuf[j].y;
            acc0.z += vbuf[j].z;     acc0.w += vbuf[j].w;
            acc1.x += vbuf[j + 1].x; acc1.y += vbuf[j + 1].y;
            acc1.z += vbuf[j + 1].z; acc1.w += vbuf[j + 1].w;
        }
    }
    acc0.x += acc1.x; acc0.y += acc1.y;
    acc0.z += acc1.z; acc0.w += acc1.w;
    *reinterpret_cast<float4*>(dst + rs * D + d4 * 4) = acc0;
}

// ============================================================
// K1b: fcrow row-sums + part1 (small, overlaps with k1_colsum).
// grid 14, block 256.
// ============================================================
__global__ void k1_misc(const float* __restrict__ fc_w,
                        const float* __restrict__ w,
                        const float* __restrict__ n_param) {
    int flat = blockIdx.x;
    int t = threadIdx.x, wid = t >> 5, lane = t & 31;
    if (flat < 13) {                                   // fcrow: 13 blocks x 8 warps
        int c = flat * 8 + wid;
        if (c < NC) {
            float s = 0.f;
            for (int j = lane; j < D; j += 32) s += fc_w[c * D + j];
#pragma unroll
            for (int o = 16; o; o >>= 1) s += __shfl_xor_sync(0xffffffffu, s, o);
            if (lane == 0) g_fcrow[c] = s;
        }
    } else if (t == 0) {
        float p1 = 0.f;
#pragma unroll
        for (int i = 0; i < 4; i++)
            p1 += w[i + 1] * n_param[i + 1] + w[i] * n_param[i];
        g_part1 = p1;
    }
}

// ============================================================
// K3: Z-build + FFMA2 GEMM -> split scratch.
// grid (8, 48) = 384 CTAs; block 320 (10 warps); occ 3 -> 30 warps/SM.
// Ping-pong register double-buffered mainloop.
// ============================================================
__global__ __launch_bounds__(320, 3)
void k3_gemm(const float* __restrict__ xf, const float* __restrict__ fc_w) {
    __shared__ float colAs[BK], colBs[BK];
    __shared__ float sm[BM * ZSTR + (BK + 1) * WTS];  // 4160+6760=10920f=43.7KB
    float* Zs = sm;                             // [64][65]
    float* Wt = sm + BM * ZSTR;                 // [65][104], cols contiguous

    const int t     = threadIdx.x;
    const int lane  = t & 31;
    const int cg    = t >> 5;                   // warp id 0..9 -> col group
    const int mtile = blockIdx.x;               // 0..7
    const int split = blockIdx.y;               // 0..47
    const int k0    = split * BK;

    // ---- prologue: per-CTA colsum finalize for cols [k0, k0+64) ----
    if (t < 128) {
        int c = t & 63;
        const float* src = (t < 64) ? g_pA : g_pB;
        float*       dst = (t < 64) ? colAs : colBs;
        float s = 0.f;
#pragma unroll 8
        for (int r = 0; r < RS; r++) s += src[r * D + k0 + c];
        dst[c] = s;
    }
    __syncthreads();

    // ---- Z tile: 64 rows x 16 quads (poly sincos, FMA pipe) ----
    for (int i = t; i < BM * (BK / 4); i += 320) {
        int row = i >> 4;
        int kq  = i & 15;
        float4 v = *reinterpret_cast<const float4*>(
            xf + (mtile * BM + row) * D + k0 + kq * 4);
        float vv[4] = {v.x, v.y, v.z, v.w};
#pragma unroll
        for (int j = 0; j < 4; j++) {
            int kk = kq * 4 + j;
            float sn, cs;
            fast_sincos(vv[j], sn, cs);
            Zs[row * ZSTR + kk] = cs * colAs[kk] + sn * colBs[kk];
        }
    }
    // ---- W tile: 100 rows x 16 quads, transposed into Wt[k][c] ----
    for (int i = t; i < NC * (BK / 4); i += 320) {
        int c  = i >> 4;
        int kq = i & 15;
        float4 v = *reinterpret_cast<const float4*>(fc_w + c * D + k0 + kq * 4);
        Wt[(kq * 4 + 0) * WTS + c] = v.x;
        Wt[(kq * 4 + 1) * WTS + c] = v.y;
        Wt[(kq * 4 + 2) * WTS + c] = v.z;
        Wt[(kq * 4 + 3) * WTS + c] = v.w;
    }
    __syncthreads();

    // ---- mainloop: K=64, ping-pong double-buffered ----
    unsigned long long acc[2][5];
#pragma unroll
    for (int m = 0; m < 2; m++)
#pragma unroll
        for (int n = 0; n < 5; n++) acc[m][n] = 0ull;

    const float* zrow0 = &Zs[lane * ZSTR];
    const float* zrow1 = &Zs[(lane + 32) * ZSTR];
    const float* wbase = &Wt[cg * 10];

    unsigned long long wva[5], wvb[5];
    float za0, za1, zb0, zb1;
    {   // preload k = 0
        const unsigned long long* wp =
            reinterpret_cast<const unsigned long long*>(wbase);
#pragma unroll
        for (int q = 0; q < 5; q++) wva[q] = wp[q];
        za0 = zrow0[0];
        za1 = zrow1[0];
    }

#pragma unroll
    for (int k = 0; k < BK; k += 2) {
        // prefetch k+1 into B
        const unsigned long long* wp1 =
            reinterpret_cast<const unsigned long long*>(wbase + (k + 1) * WTS);
#pragma unroll
        for (int q = 0; q < 5; q++) wvb[q] = wp1[q];
        zb0 = zrow0[k + 1];
        zb1 = zrow1[k + 1];
        // compute k with A
        {
            unsigned long long zz0 = pk2(za0, za0);
            unsigned long long zz1 = pk2(za1, za1);
#pragma unroll
            for (int n = 0; n < 5; n++) fma2(acc[0][n], zz0, wva[n]);
#pragma unroll
            for (int n = 0; n < 5; n++) fma2(acc[1][n], zz1, wva[n]);
        }
        // prefetch k+2 into A (k+2 == BK hits pads; loaded, never used)
        const unsigned long long* wp2 =
            reinterpret_cast<const unsigned long long*>(wbase + (k + 2) * WTS);
#pragma unroll
        for (int q = 0; q < 5; q++) wva[q] = wp2[q];
        za0 = zrow0[k + 2 > BK - 1 ? BK : k + 2];
        za1 = zrow1[k + 2 > BK - 1 ? BK : k + 2];
        // compute k+1 with B
        {
            unsigned long long zz0 = pk2(zb0, zb0);
            unsigned long long zz1 = pk2(zb1, zb1);
#pragma unroll
            for (int n = 0; n < 5; n++) fma2(acc[0][n], zz0, wvb[n]);
#pragma unroll
            for (int n = 0; n < 5; n++) fma2(acc[1][n], zz1, wvb[n]);
        }
    }
    __syncthreads();

    // ---- epilogue: stage tile -> coalesced scratch stores ----
#pragma unroll
    for (int m = 0; m < 2; m++) {
        int r = lane + 32 * m;
#pragma unroll
        for (int n = 0; n < 5; n++) {
            float2 v = up2(acc[m][n]);
            sm[r * OSTR + cg * 10 + 2 * n]     = v.x;
            sm[r * OSTR + cg * 10 + 2 * n + 1] = v.y;
        }
    }
    __syncthreads();
    {
        float* dst = g_scratch + split * (BATCH * NC) + mtile * (BM * NC);
        for (int i = t; i < BM * NC; i += 320) {
            int row = i / NC;
            int c   = i - row * NC;
            dst[i] = sm[row * OSTR + c];
        }
    }
}

// ============================================================
// K4: reduce 48 splits + part1 * fcrow + fc_b -> out.
// grid 800 x 192: 64 outputs/block, 3 slices x 16 splits, MLP-8 batches.
// ============================================================
__global__ void k4_final(const float* __restrict__ fc_b, float* __restrict__ out) {
    __shared__ float red[2][64];
    int t  = threadIdx.x;
    int il = t & 63;            // local output index
    int sl = t >> 6;            // slice 0..2
    int idx = blockIdx.x * 64 + il;
    float a0 = 0.f, a1 = 0.f, a2 = 0.f, a3 = 0.f;
#pragma unroll
    for (int bch = 0; bch < 2; bch++) {
        float v[8];
#pragma unroll
        for (int u = 0; u < 8; u++)
            v[u] = __ldcg(&g_scratch[(sl * 16 + bch * 8 + u) * (BATCH * NC) + idx]);
        a0 += v[0] + v[4];
        a1 += v[1] + v[5];
        a2 += v[2] + v[6];
        a3 += v[3] + v[7];
    }
    float s = (a0 + a1) + (a2 + a3);
    if (sl > 0) red[sl - 1][il] = s;
    __syncthreads();
    if (sl == 0) {
        s += red[0][il] + red[1][il];
        int c = idx % NC;
        out[idx] = s + g_part1 * g_fcrow[c] + fc_b[c];
    }
}

// ============================================================
extern "C" void kernel_launch(void* const* d_in, const int* in_sizes, int n_in,
                              void* d_out, int out_size) {
    const float* x       = (const float*)d_in[0];   // [512,3072]
    const float* a       = (const float*)d_in[1];   // [3072,3072,1]
    const float* b       = (const float*)d_in[2];   // [3072,3072,1]
    const float* w       = (const float*)d_in[3];   // [5]
    const float* n_param = (const float*)d_in[4];   // [5]
    const float* fc_w    = (const float*)d_in[5];   // [100,3072]
    const float* fc_b    = (const float*)d_in[6];   // [100]
    float* out = (float*)d_out;                     // [512,100]

    k1_colsum<<<dim3(3, RS, 2), 256>>>((const float4*)a, (const float4*)b);
    k1_misc<<<14, 256>>>(fc_w, w, n_param);
    k3_gemm<<<dim3(MT, NSPLIT), 320>>>(x, fc_w);
    k4_final<<<800, 192>>>(fc_b, out);
}

// round 17
// speedup vs baseline: 1.0580x; 1.0580x over previous
#include <cuda_runtime.h>

#define D      3072
#define BATCH  512
#define NC     100
#define RS     192     // row splits for column-sum kernel
#define RROWS  16      // rows per split (192*16 = 3072)
#define BK     64      // GEMM k-tile per CTA (single smem stage)
#define NSPLIT 48      // D / BK
#define BM     64      // GEMM m-tile
#define MT     8       // BATCH / BM
#define ZSTR   65      // Zs row stride (>= BK+1; 65 mod 32 = 1 -> conflict-free)
#define WTS    104     // Wt row stride (floats), 16B-aligned rows
#define OSTR   101     // epilogue staging stride

// ---- device scratch (static, no allocation) ----
__device__ float g_pA[RS * D];
__device__ float g_pB[RS * D];
__device__ float g_colA[D];
__device__ float g_colB[D];
__device__ float g_fcrow[NC];
__device__ float g_part1;
__device__ float g_scratch[NSPLIT * BATCH * NC];   // 9.8 MB

// ---- f32x2 packed-FMA helpers (sm_103a FFMA2, rt2 confirmed by profile) ----
__device__ __forceinline__ unsigned long long pk2(float lo, float hi) {
    unsigned long long r;
    asm("mov.b64 %0, {%1, %2};" : "=l"(r) : "f"(lo), "f"(hi));
    return r;
}
__device__ __forceinline__ void fma2(unsigned long long& d,
                                     unsigned long long a,
                                     unsigned long long b) {
    asm("fma.rn.f32x2 %0, %1, %2, %0;" : "+l"(d) : "l"(a), "l"(b));
}
__device__ __forceinline__ float2 up2(unsigned long long v) {
    float2 f;
    asm("mov.b64 {%0, %1}, %2;" : "=f"(f.x), "=f"(f.y) : "l"(v));
    return f;
}

// ---- FMA-pipe sincos (validated rel_err ~4.5e-7) ----
__device__ __forceinline__ void fast_sincos(float x, float& sn, float& cs) {
    const float BIGMAGIC = 12582912.0f;               // 1.5 * 2^23
    float y = fmaf(x, 0.63661977236758134f, BIGMAGIC);
    unsigned q = __float_as_uint(y);
    float n = y - BIGMAGIC;
    float r = fmaf(n, -1.57079637050628662109375f, x);
    r = fmaf(n, 4.37113900018624283e-8f, r);
    float r2 = r * r;
    float ps = fmaf(r2, -1.9515295891e-4f, 8.3321608736e-3f);
    ps = fmaf(r2, ps, -1.6666654611e-1f);
    float sinp = fmaf(r * r2, ps, r);
    float pc = fmaf(r2, 2.443315711809948e-5f, -1.388731625493765e-3f);
    pc = fmaf(r2, pc, 4.166664568298827e-2f);
    pc = fmaf(r2, pc, -0.5f);
    float cosp = fmaf(r2, pc, 1.0f);
    bool swap = (q & 1u);
    float us = swap ? cosp : sinp;
    float uc = swap ? sinp : cosp;
    sn = __uint_as_float(__float_as_uint(us) ^ ((q & 2u) << 30));
    cs = __uint_as_float(__float_as_uint(uc) ^ (((q + 1u) & 2u) << 30));
}

// ============================================================
// K1: partial column sums of a/b. grid (3, 192, 2), block 256.
// 1152 blocks ~ 7.8/SM -> ~62 warps/SM resident: latency hidden by
// warp count (per-thread MLP forcing proved unreliable in SASS).
// Each thread: 16 rows in two 8-deep batches.
// ============================================================
__global__ void k1_colsum(const float4* __restrict__ a,
                          const float4* __restrict__ b) {
    int d4 = blockIdx.x * 256 + threadIdx.x;       // 0..767
    int rs = blockIdx.y;                           // 0..191
    const float4* src = (blockIdx.z == 0) ? a : b;
    float*        dst = (blockIdx.z == 0) ? g_pA : g_pB;
    const float4* p = src + rs * RROWS * (D / 4) + d4;
    float4 acc0 = make_float4(0.f, 0.f, 0.f, 0.f);
    float4 acc1 = make_float4(0.f, 0.f, 0.f, 0.f);
    float4 vbuf[8];
#pragma unroll
    for (int batch = 0; batch < RROWS / 8; batch++) {
#pragma unroll
        for (int j = 0; j < 8; j++)
            vbuf[j] = __ldcs(&p[(batch * 8 + j) * (D / 4)]);
#pragma unroll
        for (int j = 0; j < 8; j += 2) {
            acc0.x += vbuf[j].x;     acc0.y += vbuf[j].y;
            acc0.z += vbuf[j].z;     acc0.w += vbuf[j].w;
            acc1.x += vbuf[j + 1].x; acc1.y += vbuf[j + 1].y;
            acc1.z += vbuf[j + 1].z; acc1.w += vbuf[j + 1].w;
        }
    }
    acc0.x += acc1.x; acc0.y += acc1.y;
    acc0.z += acc1.z; acc0.w += acc1.w;
    *reinterpret_cast<float4*>(dst + rs * D + d4 * 4) = acc0;
}

// ============================================================
// K2: finalize colA/colB (blocks 0..23), fcrow (24..36), part1 (37).
// grid 38, block 256. Coalesced column walks with MLP batches.
// ============================================================
__global__ void k2_prep(const float* __restrict__ fc_w,
                        const float* __restrict__ w,
                        const float* __restrict__ n_param) {
    int bx = blockIdx.x, t = threadIdx.x;
    if (bx < 24) {
        int half = bx / 12;                        // 0: A, 1: B
        int d = (bx - half * 12) * 256 + t;
        const float* src = half ? g_pB : g_pA;
        float acc0 = 0.f, acc1 = 0.f;
        float vb[8];
#pragma unroll 4
        for (int batch = 0; batch < RS / 8; batch++) {
#pragma unroll
            for (int j = 0; j < 8; j++)
                vb[j] = src[(batch * 8 + j) * D + d];
#pragma unroll
            for (int j = 0; j < 8; j += 2) {
                acc0 += vb[j];
                acc1 += vb[j + 1];
            }
        }
        (half ? g_colB : g_colA)[d] = acc0 + acc1;
    } else if (bx < 37) {                          // fcrow: 13 blocks x 8 warps
        int wid = t >> 5, lane = t & 31;
        int c = (bx - 24) * 8 + wid;
        if (c < NC) {
            float s = 0.f;
            for (int j = lane; j < D; j += 32) s += fc_w[c * D + j];
#pragma unroll
            for (int o = 16; o; o >>= 1) s += __shfl_xor_sync(0xffffffffu, s, o);
            if (lane == 0) g_fcrow[c] = s;
        }
    } else if (t == 0) {
        float p1 = 0.f;
#pragma unroll
        for (int i = 0; i < 4; i++)
            p1 += w[i + 1] * n_param[i + 1] + w[i] * n_param[i];
        g_part1 = p1;
    }
}

// ============================================================
// K3: Z-build + FFMA2 GEMM -> split scratch.
// grid (8, 48) = 384 CTAs; block 320 (10 warps); occ 3 -> 30 warps/SM.
// Prologue is now a single load per thread (colA/colB precomputed).
// Ping-pong register double-buffered mainloop.
// ============================================================
__global__ __launch_bounds__(320, 3)
void k3_gemm(const float* __restrict__ xf, const float* __restrict__ fc_w) {
    __shared__ float colAs[BK], colBs[BK];
    __shared__ float sm[BM * ZSTR + (BK + 1) * WTS];  // 4160+6760=10920f=43.7KB
    float* Zs = sm;                             // [64][65]
    float* Wt = sm + BM * ZSTR;                 // [65][104], cols contiguous

    const int t     = threadIdx.x;
    const int lane  = t & 31;
    const int cg    = t >> 5;                   // warp id 0..9 -> col group
    const int mtile = blockIdx.x;               // 0..7
    const int split = blockIdx.y;               // 0..47
    const int k0    = split * BK;

    // ---- prologue: one load per thread ----
    if (t < 128) {
        int c = t & 63;
        if (t < 64) colAs[c] = g_colA[k0 + c];
        else        colBs[c] = g_colB[k0 + c];
    }
    __syncthreads();

    // ---- Z tile: 64 rows x 16 quads (poly sincos, FMA pipe) ----
    for (int i = t; i < BM * (BK / 4); i += 320) {
        int row = i >> 4;
        int kq  = i & 15;
        float4 v = *reinterpret_cast<const float4*>(
            xf + (mtile * BM + row) * D + k0 + kq * 4);
        float vv[4] = {v.x, v.y, v.z, v.w};
#pragma unroll
        for (int j = 0; j < 4; j++) {
            int kk = kq * 4 + j;
            float sn, cs;
            fast_sincos(vv[j], sn, cs);
            Zs[row * ZSTR + kk] = cs * colAs[kk] + sn * colBs[kk];
        }
    }
    // ---- W tile: 100 rows x 16 quads, transposed into Wt[k][c] ----
    for (int i = t; i < NC * (BK / 4); i += 320) {
        int c  = i >> 4;
        int kq = i & 15;
        float4 v = *reinterpret_cast<const float4*>(fc_w + c * D + k0 + kq * 4);
        Wt[(kq * 4 + 0) * WTS + c] = v.x;
        Wt[(kq * 4 + 1) * WTS + c] = v.y;
        Wt[(kq * 4 + 2) * WTS + c] = v.z;
        Wt[(kq * 4 + 3) * WTS + c] = v.w;
    }
    __syncthreads();

    // ---- mainloop: K=64, ping-pong double-buffered ----
    unsigned long long acc[2][5];
#pragma unroll
    for (int m = 0; m < 2; m++)
#pragma unroll
        for (int n = 0; n < 5; n++) acc[m][n] = 0ull;

    const float* zrow0 = &Zs[lane * ZSTR];
    const float* zrow1 = &Zs[(lane + 32) * ZSTR];
    const float* wbase = &Wt[cg * 10];

    unsigned long long wva[5], wvb[5];
    float za0, za1, zb0, zb1;
    {   // preload k = 0
        const unsigned long long* wp =
            reinterpret_cast<const unsigned long long*>(wbase);
#pragma unroll
        for (int q = 0; q < 5; q++) wva[q] = wp[q];
        za0 = zrow0[0];
        za1 = zrow1[0];
    }

#pragma unroll
    for (int k = 0; k < BK; k += 2) {
        // prefetch k+1 into B
        const unsigned long long* wp1 =
            reinterpret_cast<const unsigned long long*>(wbase + (k + 1) * WTS);
#pragma unroll
        for (int q = 0; q < 5; q++) wvb[q] = wp1[q];
        zb0 = zrow0[k + 1];
        zb1 = zrow1[k + 1];
        // compute k with A
        {
            unsigned long long zz0 = pk2(za0, za0);
            unsigned long long zz1 = pk2(za1, za1);
#pragma unroll
            for (int n = 0; n < 5; n++) fma2(acc[0][n], zz0, wva[n]);
#pragma unroll
            for (int n = 0; n < 5; n++) fma2(acc[1][n], zz1, wva[n]);
        }
        // prefetch k+2 into A (k+2 == BK hits pads; loaded, never used)
        const unsigned long long* wp2 =
            reinterpret_cast<const unsigned long long*>(wbase + (k + 2) * WTS);
#pragma unroll
        for (int q = 0; q < 5; q++) wva[q] = wp2[q];
        za0 = zrow0[k + 2 > BK - 1 ? BK : k + 2];
        za1 = zrow1[k + 2 > BK - 1 ? BK : k + 2];
        // compute k+1 with B
        {
            unsigned long long zz0 = pk2(zb0, zb0);
            unsigned long long zz1 = pk2(zb1, zb1);
#pragma unroll
            for (int n = 0; n < 5; n++) fma2(acc[0][n], zz0, wvb[n]);
#pragma unroll
            for (int n = 0; n < 5; n++) fma2(acc[1][n], zz1, wvb[n]);
        }
    }
    __syncthreads();

    // ---- epilogue: stage tile -> coalesced scratch stores ----
#pragma unroll
    for (int m = 0; m < 2; m++) {
        int r = lane + 32 * m;
#pragma unroll
        for (int n = 0; n < 5; n++) {
            float2 v = up2(acc[m][n]);
            sm[r * OSTR + cg * 10 + 2 * n]     = v.x;
            sm[r * OSTR + cg * 10 + 2 * n + 1] = v.y;
        }
    }
    __syncthreads();
    {
        float* dst = g_scratch + split * (BATCH * NC) + mtile * (BM * NC);
        for (int i = t; i < BM * NC; i += 320) {
            int row = i / NC;
            int c   = i - row * NC;
            dst[i] = sm[row * OSTR + c];
        }
    }
}

// ============================================================
// K4: reduce 48 splits + part1 * fcrow + fc_b -> out.
// grid 800 x 192: 64 outputs/block, 3 slices x 16 splits, MLP-8 batches.
// ============================================================
__global__ void k4_final(const float* __restrict__ fc_b, float* __restrict__ out) {
    __shared__ float red[2][64];
    int t  = threadIdx.x;
    int il = t & 63;            // local output index
    int sl = t >> 6;            // slice 0..2
    int idx = blockIdx.x * 64 + il;
    float a0 = 0.f, a1 = 0.f, a2 = 0.f, a3 = 0.f;
#pragma unroll
    for (int bch = 0; bch < 2; bch++) {
        float v[8];
#pragma unroll
        for (int u = 0; u < 8; u++)
            v[u] = __ldcg(&g_scratch[(sl * 16 + bch * 8 + u) * (BATCH * NC) + idx]);
        a0 += v[0] + v[4];
        a1 += v[1] + v[5];
        a2 += v[2] + v[6];
        a3 += v[3] + v[7];
    }
    float s = (a0 + a1) + (a2 + a3);
    if (sl > 0) red[sl - 1][il] = s;
    __syncthreads();
    if (sl == 0) {
        s += red[0][il] + red[1][il];
        int c = idx % NC;
        out[idx] = s + g_part1 * g_fcrow[c] + fc_b[c];
    }
}

// ============================================================
extern "C" void kernel_launch(void* const* d_in, const int* in_sizes, int n_in,
                              void* d_out, int out_size) {
    const float* x       = (const float*)d_in[0];   // [512,3072]
    const float* a       = (const float*)d_in[1];   // [3072,3072,1]
    const float* b       = (const float*)d_in[2];   // [3072,3072,1]
    const float* w       = (const float*)d_in[3];   // [5]
    const float* n_param = (const float*)d_in[4];   // [5]
    const float* fc_w    = (const float*)d_in[5];   // [100,3072]
    const float* fc_b    = (const float*)d_in[6];   // [100]
    float* out = (float*)d_out;                     // [512,100]

    k1_colsum<<<dim3(3, RS, 2), 256>>>((const float4*)a, (const float4*)b);
    k2_prep<<<38, 256>>>(fc_w, w, n_param);
    k3_gemm<<<dim3(MT, NSPLIT), 320>>>(x, fc_w);
    k4_final<<<800, 192>>>(fc_b, out);
}